// round 16
// baseline (speedup 1.0000x reference)
#include <cuda_runtime.h>
#include <cuda_bf16.h>
#include <cstdint>

#define BB 16384
#define FF 50
#define EE 64

#define NCHUNK 4
#define CHB (BB / NCHUNK)   // 4096 batches per chunk

// Stage-1 intermediate h_out, stored as bf16 hi/lo split (105MB each).
__device__ __nv_bfloat16 g_ho_hi[(size_t)BB * FF * EE];
__device__ __nv_bfloat16 g_ho_lo[(size_t)BB * FF * EE];

// ======================= helpers =======================
__device__ __forceinline__ uint32_t smem_u32(const void* p) {
    uint32_t a;
    asm("{ .reg .u64 t; cvta.to.shared.u64 t, %1; cvt.u32.u64 %0, t; }"
        : "=r"(a) : "l"(p));
    return a;
}
__device__ __forceinline__ void ldsm4(uint32_t* r, uint32_t a) {
    asm volatile("ldmatrix.sync.aligned.m8n8.x4.shared.b16 {%0,%1,%2,%3}, [%4];"
        : "=r"(r[0]), "=r"(r[1]), "=r"(r[2]), "=r"(r[3]) : "r"(a));
}
__device__ __forceinline__ void ldsm4t(uint32_t* r, uint32_t a) {
    asm volatile("ldmatrix.sync.aligned.m8n8.x4.trans.shared.b16 {%0,%1,%2,%3}, [%4];"
        : "=r"(r[0]), "=r"(r[1]), "=r"(r[2]), "=r"(r[3]) : "r"(a));
}
__device__ __forceinline__ void mma16816(float* d, const uint32_t* a,
                                         uint32_t b0, uint32_t b1) {
    asm volatile(
        "mma.sync.aligned.m16n8k16.row.col.f32.bf16.bf16.f32 "
        "{%0,%1,%2,%3}, {%4,%5,%6,%7}, {%8,%9}, {%0,%1,%2,%3};"
        : "+f"(d[0]), "+f"(d[1]), "+f"(d[2]), "+f"(d[3])
        : "r"(a[0]), "r"(a[1]), "r"(a[2]), "r"(a[3]), "r"(b0), "r"(b1));
}
#define CP_ASYNC16(dst, src) \
    asm volatile("cp.async.cg.shared.global [%0], [%1], 16;" \
                 :: "r"(dst), "l"(src) : "memory")
#define CP_COMMIT() asm volatile("cp.async.commit_group;" ::: "memory")
#define CP_WAIT0()  asm volatile("cp.async.wait_group 0;" ::: "memory")

// Convert float4 -> bf16 hi/lo, store into [row][64]bf16 tile (128B rows,
// XOR-(row&7)<<4 permuted so ldmatrix over 8 consecutive rows is conflict-free).
__device__ __forceinline__ void split_store4(char* hiB, char* loB, int row, int c4,
                                             float4 v) {
    __nv_bfloat16 h0 = __float2bfloat16_rn(v.x);
    __nv_bfloat16 h1 = __float2bfloat16_rn(v.y);
    __nv_bfloat16 h2 = __float2bfloat16_rn(v.z);
    __nv_bfloat16 h3 = __float2bfloat16_rn(v.w);
    __nv_bfloat16 l0 = __float2bfloat16_rn(v.x - __bfloat162float(h0));
    __nv_bfloat16 l1 = __float2bfloat16_rn(v.y - __bfloat162float(h1));
    __nv_bfloat16 l2 = __float2bfloat16_rn(v.z - __bfloat162float(h2));
    __nv_bfloat16 l3 = __float2bfloat16_rn(v.w - __bfloat162float(h3));
    __nv_bfloat162 hp0 = __nv_bfloat162(h0, h1), hp1 = __nv_bfloat162(h2, h3);
    __nv_bfloat162 lp0 = __nv_bfloat162(l0, l1), lp1 = __nv_bfloat162(l2, l3);
    uint32_t byte0 = (uint32_t)(row * 128 + c4 * 8);
    uint32_t sw = byte0 ^ (((uint32_t)row & 7u) << 4);
    *reinterpret_cast<uint32_t*>(hiB + sw)     = *reinterpret_cast<uint32_t*>(&hp0);
    *reinterpret_cast<uint32_t*>(hiB + sw + 4) = *reinterpret_cast<uint32_t*>(&hp1);
    *reinterpret_cast<uint32_t*>(loB + sw)     = *reinterpret_cast<uint32_t*>(&lp0);
    *reinterpret_cast<uint32_t*>(loB + sw + 4) = *reinterpret_cast<uint32_t*>(&lp1);
}

// ============================================================================
// Stage 1 / Stage 3: per-field GEMM, M=64 tiles (round-13/15 measured kernels).
//   Y[b,i] = sum_j X[b,j] * W[f,i,j]
// MODE 0: write bf16 hi/lo split. MODE 1: write fp32 + bias, IN-PLACE on out.
// Operates on ONE batch chunk: X/Yf/Yhi/Ylo pointers pre-offset by the caller.
// Grid (FF, CHB/64), f = blockIdx.x.
// ============================================================================
#define F_XHI 0
#define F_XLO 8192
#define F_WHI 16384
#define F_WLO 24576
#define F_BIAS 32768
#define F_SMEM 33024

template <int MODE>
__global__ __launch_bounds__(128, 6) void field64_mma(
    const float* __restrict__ X, const float* __restrict__ W,
    const float* __restrict__ bias, float* __restrict__ Yf,
    __nv_bfloat16* __restrict__ Yhi, __nv_bfloat16* __restrict__ Ylo) {
    extern __shared__ char smem[];
    const uint32_t sb = smem_u32(smem);
    const int tid = threadIdx.x, w = tid >> 5, l = tid & 31;
    const int f = blockIdx.x, b0 = blockIdx.y * 64;

    if (MODE == 1 && tid < 16)
        reinterpret_cast<float4*>(smem + F_BIAS)[tid] =
            reinterpret_cast<const float4*>(bias)[tid];

    const float* Xb = X + (size_t)b0 * (FF * EE) + (size_t)f * EE;
#pragma unroll
    for (int t = 0; t < 8; t++) {
        int idx = tid + t * 128;
        int b = idx >> 4, c4 = idx & 15;
        float4 v = *reinterpret_cast<const float4*>(Xb + (size_t)b * (FF * EE) + c4 * 4);
        split_store4(smem + F_XHI, smem + F_XLO, b, c4, v);
    }
    const float* Wf = W + (size_t)f * EE * EE;
#pragma unroll
    for (int t = 0; t < 8; t++) {
        int idx = tid + t * 128;
        int n = idx >> 4, c4 = idx & 15;
        float4 v = *reinterpret_cast<const float4*>(Wf + n * EE + c4 * 4);
        split_store4(smem + F_WHI, smem + F_WLO, n, c4, v);
    }
    __syncthreads();

    const int arow = w * 16 + (l & 15);
    const int achk = l >> 4;
    const int brow = (l & 7) + ((l >> 4) << 3);
    const int bchk = (l >> 3) & 1;

    float D[8][4] = {};

#pragma unroll
    for (int ks = 0; ks < 4; ks++) {
        uint32_t Ahi[4], Alo[4];
        uint32_t aoff = (uint32_t)(arow * 128) +
                        ((uint32_t)((2 * ks + achk) ^ (arow & 7)) << 4);
        ldsm4(Ahi, sb + F_XHI + aoff);
        ldsm4(Alo, sb + F_XLO + aoff);
#pragma unroll
        for (int p = 0; p < 4; p++) {
            int nrow = p * 16 + brow;
            uint32_t boff = (uint32_t)(nrow * 128) +
                            ((uint32_t)((2 * ks + bchk) ^ (nrow & 7)) << 4);
            uint32_t Bhi[4], Blo[4];
            ldsm4(Bhi, sb + F_WHI + boff);
            ldsm4(Blo, sb + F_WLO + boff);
            mma16816(D[2 * p],     Ahi, Bhi[0], Bhi[1]);
            mma16816(D[2 * p],     Ahi, Blo[0], Blo[1]);
            mma16816(D[2 * p],     Alo, Bhi[0], Bhi[1]);
            mma16816(D[2 * p + 1], Ahi, Bhi[2], Bhi[3]);
            mma16816(D[2 * p + 1], Ahi, Blo[2], Blo[3]);
            mma16816(D[2 * p + 1], Alo, Bhi[2], Bhi[3]);
        }
    }

    __syncthreads();   // done reading X/W smem for this tile
    const int r0 = l >> 2, c0 = (l & 3) * 2;
    if (MODE == 0) {
#pragma unroll
        for (int half = 0; half < 2; half++) {
            int rl = w * 16 + half * 8 + r0;
            uint32_t rsw = ((uint32_t)rl & 7u) << 4;
#pragma unroll
            for (int nt = 0; nt < 8; nt++) {
                float vx = D[nt][2 * half], vy = D[nt][2 * half + 1];
                __nv_bfloat16 h0 = __float2bfloat16_rn(vx);
                __nv_bfloat16 h1 = __float2bfloat16_rn(vy);
                __nv_bfloat16 l0 = __float2bfloat16_rn(vx - __bfloat162float(h0));
                __nv_bfloat16 l1 = __float2bfloat16_rn(vy - __bfloat162float(h1));
                __nv_bfloat162 hp = __nv_bfloat162(h0, h1);
                __nv_bfloat162 lp = __nv_bfloat162(l0, l1);
                uint32_t off = (uint32_t)(rl * 128) +
                               (((uint32_t)((nt * 8 + c0) * 2)) ^ rsw);
                *reinterpret_cast<uint32_t*>(smem + F_XHI + off) =
                    *reinterpret_cast<uint32_t*>(&hp);
                *reinterpret_cast<uint32_t*>(smem + F_XLO + off) =
                    *reinterpret_cast<uint32_t*>(&lp);
            }
        }
        __syncthreads();
#pragma unroll
        for (int it = 0; it < 4; it++) {
            int idx = tid + it * 128;
            int rl = idx >> 3, u = idx & 7;
            uint32_t off = (uint32_t)(rl * 128) +
                           (((uint32_t)(u * 16)) ^ (((uint32_t)rl & 7u) << 4));
            uint4 vhi = *reinterpret_cast<const uint4*>(smem + F_XHI + off);
            uint4 vlo = *reinterpret_cast<const uint4*>(smem + F_XLO + off);
            size_t base = ((size_t)(b0 + rl) * FF + f) * EE + u * 8;
            *reinterpret_cast<uint4*>(Yhi + base) = vhi;
            *reinterpret_cast<uint4*>(Ylo + base) = vlo;
        }
    } else {
#pragma unroll
        for (int half = 0; half < 2; half++) {
            int rl = w * 16 + half * 8 + r0;
            uint32_t rsw = ((uint32_t)rl & 7u) << 4;
#pragma unroll
            for (int nt = 0; nt < 8; nt++) {
                float2 v = make_float2(D[nt][2 * half], D[nt][2 * half + 1]);
                uint32_t off = (uint32_t)(rl * 256) +
                               (((uint32_t)((nt * 8 + c0) * 4)) ^ rsw);
                *reinterpret_cast<float2*>(smem + F_XHI + off) = v;
            }
        }
        __syncthreads();
        const float* bsm = reinterpret_cast<const float*>(smem + F_BIAS);
#pragma unroll
        for (int it = 0; it < 8; it++) {
            int idx = tid + it * 128;
            int rl = idx >> 4, u = idx & 15;
            uint32_t off = (uint32_t)(rl * 256) +
                           (((uint32_t)(u * 16)) ^ (((uint32_t)rl & 7u) << 4));
            float4 v = *reinterpret_cast<const float4*>(smem + F_XHI + off);
            v.x += bsm[u * 4 + 0];
            v.y += bsm[u * 4 + 1];
            v.z += bsm[u * 4 + 2];
            v.w += bsm[u * 4 + 3];
            size_t base = ((size_t)(b0 + rl) * FF + f) * EE + u * 4;
            *reinterpret_cast<float4*>(Yf + base) = v;
        }
    }
}

// ============================================================================
// Stage 2: PERSISTENT double-buffered aggregation over [b_start, b_end).
//   out[b,f,e] = sum_g G[b,f,g] * HO[b,g,e]   -> fp32 into d_out
// (round-9/10 measured form; chunk bounds from round 14.)
// ============================================================================
#define HOF(s)  ((s) * 16384)
#define AGF_HI  32768
#define AGF_LO  40960
#define GRAW(s) (49152 + (s) * 10240)
#define A_SMEM  69632
#define AGGR_GRID 444

__global__ __launch_bounds__(128) void aggr_mma(
    const float* __restrict__ Gm,
    const __nv_bfloat16* __restrict__ HOhi, const __nv_bfloat16* __restrict__ HOlo,
    float* __restrict__ out, int b_start, int b_end) {
    extern __shared__ char smem[];
    const uint32_t sb = smem_u32(smem);
    const int tid = threadIdx.x, w = tid >> 5, l = tid & 31;

    const uint4 z4 = make_uint4(0, 0, 0, 0);
    for (int i = tid; i < 1024; i += 128)
        reinterpret_cast<uint4*>(smem + AGF_HI)[i] = z4;
    for (int i = tid; i < 448; i += 128) {
        int s = i / 224, r = i - s * 224;
        int half = r / 112, rr = r - half * 112;
        int g = 50 + (rr >> 3), u = rr & 7;
        uint32_t off = (uint32_t)(g * 128 + u * 16) ^ (((uint32_t)g & 7u) << 4);
        *reinterpret_cast<uint4*>(smem + HOF(s) + half * 8192 + off) = z4;
    }
    __syncthreads();

    const int arow  = w * 16 + (l & 15);
    const int achk  = l >> 4;
    const int bkrow = (l & 7) + (((l >> 3) & 1) << 3);
    const int bchk  = l >> 4;
    const uint32_t aoff_base = (uint32_t)(arow * 128);

    int b0 = b_start + blockIdx.x;
    auto issue_loads = [&](int b, int st) {
        for (int i = tid; i < 800; i += 128) {
            int half = (i >= 400);
            int rr = i - half * 400;
            int g = rr >> 3, u = rr & 7;
            const __nv_bfloat16* src = (half ? HOlo : HOhi) +
                ((size_t)b * FF + g) * EE + u * 8;
            uint32_t off = (uint32_t)(g * 128 + u * 16) ^ (((uint32_t)g & 7u) << 4);
            CP_ASYNC16(sb + HOF(st) + half * 8192 + off, src);
        }
        for (int i = tid; i < 625; i += 128)
            CP_ASYNC16(sb + GRAW(st) + i * 16, Gm + (size_t)b * (FF * FF) + i * 4);
    };

    if (b0 < b_end) issue_loads(b0, 0);
    CP_COMMIT();

    int s = 0;
    for (int b = b0; b < b_end; b += AGGR_GRID) {
        CP_WAIT0();
        __syncthreads();

        int nb = b + AGGR_GRID;
        if (nb < b_end) issue_loads(nb, s ^ 1);
        CP_COMMIT();

        const char* graw = smem + GRAW(s);
        for (int i = tid; i < 1250; i += 128) {
            int fq = i / 25, g2 = i - fq * 25;
            float2 v = *reinterpret_cast<const float2*>(graw + (fq * 50 + g2 * 2) * 4);
            __nv_bfloat16 h0 = __float2bfloat16_rn(v.x);
            __nv_bfloat16 h1 = __float2bfloat16_rn(v.y);
            __nv_bfloat16 l0 = __float2bfloat16_rn(v.x - __bfloat162float(h0));
            __nv_bfloat16 l1 = __float2bfloat16_rn(v.y - __bfloat162float(h1));
            __nv_bfloat162 hp = __nv_bfloat162(h0, h1);
            __nv_bfloat162 lp = __nv_bfloat162(l0, l1);
            uint32_t off = (uint32_t)(fq * 128 + g2 * 4) ^ (((uint32_t)fq & 7u) << 4);
            *reinterpret_cast<uint32_t*>(smem + AGF_HI + off) =
                *reinterpret_cast<uint32_t*>(&hp);
            *reinterpret_cast<uint32_t*>(smem + AGF_LO + off) =
                *reinterpret_cast<uint32_t*>(&lp);
        }
        __syncthreads();

        float D[8][4] = {};
#pragma unroll
        for (int ks = 0; ks < 4; ks++) {
            uint32_t Ahi[4], Alo[4];
            uint32_t aoff = aoff_base +
                            ((uint32_t)((2 * ks + achk) ^ (arow & 7)) << 4);
            ldsm4(Ahi, sb + AGF_HI + aoff);
            ldsm4(Alo, sb + AGF_LO + aoff);
#pragma unroll
            for (int p = 0; p < 4; p++) {
                int krow = ks * 16 + bkrow;
                uint32_t boff = (uint32_t)(krow * 128) +
                                ((uint32_t)((2 * p + bchk) ^ (krow & 7)) << 4);
                uint32_t Bhi[4], Blo[4];
                ldsm4t(Bhi, sb + HOF(s) + boff);
                ldsm4t(Blo, sb + HOF(s) + 8192 + boff);
                mma16816(D[2 * p],     Ahi, Bhi[0], Bhi[1]);
                mma16816(D[2 * p],     Ahi, Blo[0], Blo[1]);
                mma16816(D[2 * p],     Alo, Bhi[0], Bhi[1]);
                mma16816(D[2 * p + 1], Ahi, Bhi[2], Bhi[3]);
                mma16816(D[2 * p + 1], Ahi, Blo[2], Blo[3]);
                mma16816(D[2 * p + 1], Alo, Bhi[2], Bhi[3]);
            }
        }

        const int r0 = l >> 2, c0 = (l & 3) * 2;
#pragma unroll
        for (int half = 0; half < 2; half++) {
            int frow = w * 16 + r0 + half * 8;
            if (frow < FF) {
                float* orow = out + (size_t)b * (FF * EE) + frow * EE;
#pragma unroll
                for (int nt = 0; nt < 8; nt++)
                    *reinterpret_cast<float2*>(orow + nt * 8 + c0) =
                        make_float2(D[nt][2 * half], D[nt][2 * half + 1]);
            }
        }
        __syncthreads();
        s ^= 1;
    }
}

extern "C" void kernel_launch(void* const* d_in, const int* in_sizes, int n_in,
                              void* d_out, int out_size) {
    const float* g     = (const float*)d_in[0];   // [B,F,F]
    const float* h     = (const float*)d_in[1];   // [B,F,E]
    const float* W_in  = (const float*)d_in[2];   // [F,E,E]
    const float* W_out = (const float*)d_in[3];   // [F,E,E]
    const float* bias  = (const float*)d_in[4];   // [E]
    float* out = (float*)d_out;                   // [B,F,E]

    __nv_bfloat16 *hohi = nullptr, *holo = nullptr;
    cudaGetSymbolAddress((void**)&hohi, g_ho_hi);
    cudaGetSymbolAddress((void**)&holo, g_ho_lo);

    cudaFuncSetAttribute((const void*)field64_mma<0>,
                         cudaFuncAttributeMaxDynamicSharedMemorySize, F_SMEM);
    cudaFuncSetAttribute((const void*)field64_mma<1>,
                         cudaFuncAttributeMaxDynamicSharedMemorySize, F_SMEM);
    cudaFuncSetAttribute((const void*)aggr_mma,
                         cudaFuncAttributeMaxDynamicSharedMemorySize, A_SMEM);

    // Serial per-chunk pipeline on the default stream: each chunk's ho (52MB)
    // and out (52MB) stay L2-resident between producer and consumer launches,
    // turning the ho and out re-reads into L2 hits (L2 persists across
    // launches; only L1D is flushed per launch).
    const dim3 fgrid(FF, CHB / 64);
    for (int c = 0; c < NCHUNK; c++) {
        const size_t off = (size_t)c * CHB * FF * EE;
        // Stage 1 chunk: ho(hi/lo) = split( W_out transform of h chunk )
        field64_mma<0><<<fgrid, 128, F_SMEM>>>(
            h + off, W_out, nullptr, nullptr, hohi + off, holo + off);
        // Stage 2 chunk: out = G @ ho   (persistent pipeline over the chunk)
        aggr_mma<<<AGGR_GRID, 128, A_SMEM>>>(
            g, hohi, holo, out, c * CHB, (c + 1) * CHB);
        // Stage 3 chunk (in-place): out = W_in transform of out + bias
        field64_mma<1><<<fgrid, 128, F_SMEM>>>(
            out + off, W_in, bias, out + off, nullptr, nullptr);
    }
}

// round 17
// speedup vs baseline: 1.2243x; 1.2243x over previous
#include <cuda_runtime.h>
#include <cuda_bf16.h>
#include <cuda_fp16.h>
#include <cstdint>

#define BB 16384
#define FF 50
#define EE 64

// Stage-1 intermediate h_out, stored as SINGLE fp16 (105MB).
__device__ __half g_ho[(size_t)BB * FF * EE];

// ======================= helpers =======================
__device__ __forceinline__ uint32_t smem_u32(const void* p) {
    uint32_t a;
    asm("{ .reg .u64 t; cvta.to.shared.u64 t, %1; cvt.u32.u64 %0, t; }"
        : "=r"(a) : "l"(p));
    return a;
}
__device__ __forceinline__ void ldsm4(uint32_t* r, uint32_t a) {
    asm volatile("ldmatrix.sync.aligned.m8n8.x4.shared.b16 {%0,%1,%2,%3}, [%4];"
        : "=r"(r[0]), "=r"(r[1]), "=r"(r[2]), "=r"(r[3]) : "r"(a));
}
__device__ __forceinline__ void ldsm4t(uint32_t* r, uint32_t a) {
    asm volatile("ldmatrix.sync.aligned.m8n8.x4.trans.shared.b16 {%0,%1,%2,%3}, [%4];"
        : "=r"(r[0]), "=r"(r[1]), "=r"(r[2]), "=r"(r[3]) : "r"(a));
}
// bf16 mma (stage 1 / stage 3)
__device__ __forceinline__ void mma16816(float* d, const uint32_t* a,
                                         uint32_t b0, uint32_t b1) {
    asm volatile(
        "mma.sync.aligned.m16n8k16.row.col.f32.bf16.bf16.f32 "
        "{%0,%1,%2,%3}, {%4,%5,%6,%7}, {%8,%9}, {%0,%1,%2,%3};"
        : "+f"(d[0]), "+f"(d[1]), "+f"(d[2]), "+f"(d[3])
        : "r"(a[0]), "r"(a[1]), "r"(a[2]), "r"(a[3]), "r"(b0), "r"(b1));
}
// fp16 mma (stage 2)
__device__ __forceinline__ void mma16816h(float* d, const uint32_t* a,
                                          uint32_t b0, uint32_t b1) {
    asm volatile(
        "mma.sync.aligned.m16n8k16.row.col.f32.f16.f16.f32 "
        "{%0,%1,%2,%3}, {%4,%5,%6,%7}, {%8,%9}, {%0,%1,%2,%3};"
        : "+f"(d[0]), "+f"(d[1]), "+f"(d[2]), "+f"(d[3])
        : "r"(a[0]), "r"(a[1]), "r"(a[2]), "r"(a[3]), "r"(b0), "r"(b1));
}
#define CP_ASYNC16(dst, src) \
    asm volatile("cp.async.cg.shared.global [%0], [%1], 16;" \
                 :: "r"(dst), "l"(src) : "memory")
#define CP_COMMIT() asm volatile("cp.async.commit_group;" ::: "memory")
#define CP_WAIT0()  asm volatile("cp.async.wait_group 0;" ::: "memory")

// Convert float4 -> bf16 hi/lo, store into [row][64]bf16 tile (128B rows,
// XOR-(row&7)<<4 permuted so ldmatrix over 8 consecutive rows is conflict-free).
__device__ __forceinline__ void split_store4(char* hiB, char* loB, int row, int c4,
                                             float4 v) {
    __nv_bfloat16 h0 = __float2bfloat16_rn(v.x);
    __nv_bfloat16 h1 = __float2bfloat16_rn(v.y);
    __nv_bfloat16 h2 = __float2bfloat16_rn(v.z);
    __nv_bfloat16 h3 = __float2bfloat16_rn(v.w);
    __nv_bfloat16 l0 = __float2bfloat16_rn(v.x - __bfloat162float(h0));
    __nv_bfloat16 l1 = __float2bfloat16_rn(v.y - __bfloat162float(h1));
    __nv_bfloat16 l2 = __float2bfloat16_rn(v.z - __bfloat162float(h2));
    __nv_bfloat16 l3 = __float2bfloat16_rn(v.w - __bfloat162float(h3));
    __nv_bfloat162 hp0 = __nv_bfloat162(h0, h1), hp1 = __nv_bfloat162(h2, h3);
    __nv_bfloat162 lp0 = __nv_bfloat162(l0, l1), lp1 = __nv_bfloat162(l2, l3);
    uint32_t byte0 = (uint32_t)(row * 128 + c4 * 8);
    uint32_t sw = byte0 ^ (((uint32_t)row & 7u) << 4);
    *reinterpret_cast<uint32_t*>(hiB + sw)     = *reinterpret_cast<uint32_t*>(&hp0);
    *reinterpret_cast<uint32_t*>(hiB + sw + 4) = *reinterpret_cast<uint32_t*>(&hp1);
    *reinterpret_cast<uint32_t*>(loB + sw)     = *reinterpret_cast<uint32_t*>(&lp0);
    *reinterpret_cast<uint32_t*>(loB + sw + 4) = *reinterpret_cast<uint32_t*>(&lp1);
}

// ============================================================================
// Stage 1 / Stage 3: per-field GEMM, M=64 tiles (round-13/15 measured config).
//   Y[b,i] = sum_j X[b,j] * W[f,i,j]      (bf16-split 3-term mainloop)
// MODE 0: round result to SINGLE fp16 and write Yh (feeds stage 2).
// MODE 1: write fp32 + bias, IN-PLACE on out.
// Grid (FF, B/64), 128 threads, occ 6.
// ============================================================================
#define F_XHI 0
#define F_XLO 8192
#define F_WHI 16384
#define F_WLO 24576
#define F_BIAS 32768
#define F_SMEM 33024

template <int MODE>
__global__ __launch_bounds__(128, 6) void field64_mma(
    const float* __restrict__ X, const float* __restrict__ W,
    const float* __restrict__ bias, float* __restrict__ Yf,
    __half* __restrict__ Yh) {
    extern __shared__ char smem[];
    const uint32_t sb = smem_u32(smem);
    const int tid = threadIdx.x, w = tid >> 5, l = tid & 31;
    const int f = blockIdx.x, b0 = blockIdx.y * 64;

    if (MODE == 1 && tid < 16)
        reinterpret_cast<float4*>(smem + F_BIAS)[tid] =
            reinterpret_cast<const float4*>(bias)[tid];

    const float* Xb = X + (size_t)b0 * (FF * EE) + (size_t)f * EE;
#pragma unroll
    for (int t = 0; t < 8; t++) {
        int idx = tid + t * 128;
        int b = idx >> 4, c4 = idx & 15;
        float4 v = *reinterpret_cast<const float4*>(Xb + (size_t)b * (FF * EE) + c4 * 4);
        split_store4(smem + F_XHI, smem + F_XLO, b, c4, v);
    }
    const float* Wf = W + (size_t)f * EE * EE;
#pragma unroll
    for (int t = 0; t < 8; t++) {
        int idx = tid + t * 128;
        int n = idx >> 4, c4 = idx & 15;
        float4 v = *reinterpret_cast<const float4*>(Wf + n * EE + c4 * 4);
        split_store4(smem + F_WHI, smem + F_WLO, n, c4, v);
    }
    __syncthreads();

    const int arow = w * 16 + (l & 15);
    const int achk = l >> 4;
    const int brow = (l & 7) + ((l >> 4) << 3);
    const int bchk = (l >> 3) & 1;

    float D[8][4] = {};

#pragma unroll
    for (int ks = 0; ks < 4; ks++) {
        uint32_t Ahi[4], Alo[4];
        uint32_t aoff = (uint32_t)(arow * 128) +
                        ((uint32_t)((2 * ks + achk) ^ (arow & 7)) << 4);
        ldsm4(Ahi, sb + F_XHI + aoff);
        ldsm4(Alo, sb + F_XLO + aoff);
#pragma unroll
        for (int p = 0; p < 4; p++) {
            int nrow = p * 16 + brow;
            uint32_t boff = (uint32_t)(nrow * 128) +
                            ((uint32_t)((2 * ks + bchk) ^ (nrow & 7)) << 4);
            uint32_t Bhi[4], Blo[4];
            ldsm4(Bhi, sb + F_WHI + boff);
            ldsm4(Blo, sb + F_WLO + boff);
            mma16816(D[2 * p],     Ahi, Bhi[0], Bhi[1]);
            mma16816(D[2 * p],     Ahi, Blo[0], Blo[1]);
            mma16816(D[2 * p],     Alo, Bhi[0], Bhi[1]);
            mma16816(D[2 * p + 1], Ahi, Bhi[2], Bhi[3]);
            mma16816(D[2 * p + 1], Ahi, Blo[2], Blo[3]);
            mma16816(D[2 * p + 1], Alo, Bhi[2], Bhi[3]);
        }
    }

    __syncthreads();   // done reading X/W smem for this tile
    const int r0 = l >> 2, c0 = (l & 3) * 2;
    if (MODE == 0) {
        // Round to single fp16, stage [64][128B] swizzled, coalesced writeback.
#pragma unroll
        for (int half = 0; half < 2; half++) {
            int rl = w * 16 + half * 8 + r0;
            uint32_t rsw = ((uint32_t)rl & 7u) << 4;
#pragma unroll
            for (int nt = 0; nt < 8; nt++) {
                __half2 hp = __halves2half2(__float2half_rn(D[nt][2 * half]),
                                            __float2half_rn(D[nt][2 * half + 1]));
                uint32_t off = (uint32_t)(rl * 128) +
                               (((uint32_t)((nt * 8 + c0) * 2)) ^ rsw);
                *reinterpret_cast<uint32_t*>(smem + F_XHI + off) =
                    *reinterpret_cast<uint32_t*>(&hp);
            }
        }
        __syncthreads();
#pragma unroll
        for (int it = 0; it < 4; it++) {
            int idx = tid + it * 128;    // 0..511
            int rl = idx >> 3, u = idx & 7;
            uint32_t off = (uint32_t)(rl * 128) +
                           (((uint32_t)(u * 16)) ^ (((uint32_t)rl & 7u) << 4));
            uint4 vh = *reinterpret_cast<const uint4*>(smem + F_XHI + off);
            size_t base = ((size_t)(b0 + rl) * FF + f) * EE + u * 8;
            *reinterpret_cast<uint4*>(Yh + base) = vh;
        }
    } else {
#pragma unroll
        for (int half = 0; half < 2; half++) {
            int rl = w * 16 + half * 8 + r0;
            uint32_t rsw = ((uint32_t)rl & 7u) << 4;
#pragma unroll
            for (int nt = 0; nt < 8; nt++) {
                float2 v = make_float2(D[nt][2 * half], D[nt][2 * half + 1]);
                uint32_t off = (uint32_t)(rl * 256) +
                               (((uint32_t)((nt * 8 + c0) * 4)) ^ rsw);
                *reinterpret_cast<float2*>(smem + F_XHI + off) = v;
            }
        }
        __syncthreads();
        const float* bsm = reinterpret_cast<const float*>(smem + F_BIAS);
#pragma unroll
        for (int it = 0; it < 8; it++) {
            int idx = tid + it * 128;
            int rl = idx >> 4, u = idx & 15;
            uint32_t off = (uint32_t)(rl * 256) +
                           (((uint32_t)(u * 16)) ^ (((uint32_t)rl & 7u) << 4));
            float4 v = *reinterpret_cast<const float4*>(smem + F_XHI + off);
            v.x += bsm[u * 4 + 0];
            v.y += bsm[u * 4 + 1];
            v.z += bsm[u * 4 + 2];
            v.w += bsm[u * 4 + 3];
            size_t base = ((size_t)(b0 + rl) * FF + f) * EE + u * 4;
            *reinterpret_cast<float4*>(Yf + base) = v;
        }
    }
}

// ============================================================================
// Stage 2: PERSISTENT double-buffered aggregation, fp16 2-term.
//   out[b,f,e] = sum_g G[b,f,g] * HO[b,g,e]
// G split fp16 hi/lo in-kernel (exact); HO single fp16 ->
//   D = Ghi*HO + Glo*HO   (2 mma terms; error = HO's fp16 rounding only).
// smem 52KB -> occ 4, grid 592.
// ============================================================================
#define HOF(s)  ((s) * 8192)                 // fp16 HO tile, 64 rows x 128B
#define AGF_HI  16384
#define AGF_LO  24576
#define GRAW(s) (32768 + (s) * 10240)        // 10000B raw fp32 G
#define A_SMEM  53248
#define AGGR_GRID 592

__global__ __launch_bounds__(128) void aggr_mma(
    const float* __restrict__ Gm, const __half* __restrict__ HO,
    float* __restrict__ out) {
    extern __shared__ char smem[];
    const uint32_t sb = smem_u32(smem);
    const int tid = threadIdx.x, w = tid >> 5, l = tid & 31;

    const uint4 z4 = make_uint4(0, 0, 0, 0);
    // Zero G hi/lo regions entirely (pads f>=50 / g>=50 stay 0 forever).
    for (int i = tid; i < 1024; i += 128)
        reinterpret_cast<uint4*>(smem + AGF_HI)[i] = z4;
    // Zero HO pad rows 50..63 (both stages; never overwritten by copies).
    for (int i = tid; i < 224; i += 128) {
        int s = i / 112, rr = i - s * 112;
        int g = 50 + (rr >> 3), u = rr & 7;
        uint32_t off = (uint32_t)(g * 128 + u * 16) ^ (((uint32_t)g & 7u) << 4);
        *reinterpret_cast<uint4*>(smem + HOF(s) + off) = z4;
    }
    __syncthreads();

    const int arow  = w * 16 + (l & 15);
    const int achk  = l >> 4;
    const int bkrow = (l & 7) + (((l >> 3) & 1) << 3);
    const int bchk  = l >> 4;
    const uint32_t aoff_base = (uint32_t)(arow * 128);

    int b0 = blockIdx.x;
    auto issue_loads = [&](int b, int st) {
        // HO fp16: 50 rows x 8 x 16B, pure copies into swizzled slots.
        for (int i = tid; i < 400; i += 128) {
            int g = i >> 3, u = i & 7;
            const __half* src = HO + ((size_t)b * FF + g) * EE + u * 8;
            uint32_t off = (uint32_t)(g * 128 + u * 16) ^ (((uint32_t)g & 7u) << 4);
            CP_ASYNC16(sb + HOF(st) + off, src);
        }
        // G raw fp32: 625 x 16B contiguous.
        for (int i = tid; i < 625; i += 128)
            CP_ASYNC16(sb + GRAW(st) + i * 16, Gm + (size_t)b * (FF * FF) + i * 4);
    };

    if (b0 < BB) issue_loads(b0, 0);
    CP_COMMIT();

    int s = 0;
    for (int b = b0; b < BB; b += AGGR_GRID) {
        CP_WAIT0();
        __syncthreads();

        int nb = b + AGGR_GRID;
        if (nb < BB) issue_loads(nb, s ^ 1);
        CP_COMMIT();

        // Convert G raw fp32 -> fp16 hi/lo (exact split of fp32 values).
        const char* graw = smem + GRAW(s);
        for (int i = tid; i < 1250; i += 128) {
            int fq = i / 25, g2 = i - fq * 25;
            float2 v = *reinterpret_cast<const float2*>(graw + (fq * 50 + g2 * 2) * 4);
            __half h0 = __float2half_rn(v.x);
            __half h1 = __float2half_rn(v.y);
            __half l0 = __float2half_rn(v.x - __half2float(h0));
            __half l1 = __float2half_rn(v.y - __half2float(h1));
            __half2 hp = __halves2half2(h0, h1);
            __half2 lp = __halves2half2(l0, l1);
            uint32_t off = (uint32_t)(fq * 128 + g2 * 4) ^ (((uint32_t)fq & 7u) << 4);
            *reinterpret_cast<uint32_t*>(smem + AGF_HI + off) =
                *reinterpret_cast<uint32_t*>(&hp);
            *reinterpret_cast<uint32_t*>(smem + AGF_LO + off) =
                *reinterpret_cast<uint32_t*>(&lp);
        }
        __syncthreads();

        float D[8][4] = {};
#pragma unroll
        for (int ks = 0; ks < 4; ks++) {
            uint32_t Ghi[4], Glo[4];
            uint32_t aoff = aoff_base +
                            ((uint32_t)((2 * ks + achk) ^ (arow & 7)) << 4);
            ldsm4(Ghi, sb + AGF_HI + aoff);
            ldsm4(Glo, sb + AGF_LO + aoff);
#pragma unroll
            for (int p = 0; p < 4; p++) {
                int krow = ks * 16 + bkrow;
                uint32_t boff = (uint32_t)(krow * 128) +
                                ((uint32_t)((2 * p + bchk) ^ (krow & 7)) << 4);
                uint32_t Hv[4];
                ldsm4t(Hv, sb + HOF(s) + boff);
                mma16816h(D[2 * p],     Ghi, Hv[0], Hv[1]);
                mma16816h(D[2 * p],     Glo, Hv[0], Hv[1]);
                mma16816h(D[2 * p + 1], Ghi, Hv[2], Hv[3]);
                mma16816h(D[2 * p + 1], Glo, Hv[2], Hv[3]);
            }
        }

        const int r0 = l >> 2, c0 = (l & 3) * 2;
#pragma unroll
        for (int half = 0; half < 2; half++) {
            int frow = w * 16 + r0 + half * 8;
            if (frow < FF) {
                float* orow = out + (size_t)b * (FF * EE) + frow * EE;
#pragma unroll
                for (int nt = 0; nt < 8; nt++)
                    *reinterpret_cast<float2*>(orow + nt * 8 + c0) =
                        make_float2(D[nt][2 * half], D[nt][2 * half + 1]);
            }
        }
        __syncthreads();
        s ^= 1;
    }
}

extern "C" void kernel_launch(void* const* d_in, const int* in_sizes, int n_in,
                              void* d_out, int out_size) {
    const float* g     = (const float*)d_in[0];   // [B,F,F]
    const float* h     = (const float*)d_in[1];   // [B,F,E]
    const float* W_in  = (const float*)d_in[2];   // [F,E,E]
    const float* W_out = (const float*)d_in[3];   // [F,E,E]
    const float* bias  = (const float*)d_in[4];   // [E]
    float* out = (float*)d_out;                   // [B,F,E]

    __half* ho = nullptr;
    cudaGetSymbolAddress((void**)&ho, g_ho);

    cudaFuncSetAttribute((const void*)field64_mma<0>,
                         cudaFuncAttributeMaxDynamicSharedMemorySize, F_SMEM);
    cudaFuncSetAttribute((const void*)field64_mma<1>,
                         cudaFuncAttributeMaxDynamicSharedMemorySize, F_SMEM);
    cudaFuncSetAttribute((const void*)aggr_mma,
                         cudaFuncAttributeMaxDynamicSharedMemorySize, A_SMEM);

    const dim3 fgrid(FF, BB / 64);
    // Stage 1: ho = fp16( einsum('fij,bfj->bfi', W_out, h) )
    field64_mma<0><<<fgrid, 128, F_SMEM>>>(h, W_out, nullptr, nullptr, ho);
    // Stage 2: out = einsum('bfg,bge->bfe', g, ho)   (persistent, fp16 2-term)
    aggr_mma<<<AGGR_GRID, 128, A_SMEM>>>(g, ho, out);
    // Stage 3 (in-place): out = einsum('fij,bfj->bfi', W_in, out) + bias
    field64_mma<1><<<fgrid, 128, F_SMEM>>>(out, W_in, bias, out, nullptr);
}